// round 15
// baseline (speedup 1.0000x reference)
#include <cuda_runtime.h>
#include <math.h>

#define HIN 228
#define WIN 304
#define HG 76
#define WG 102
#define NN 7752
#define BB 2
#define KK 16
#define NCH 4
#define CHSZ (NN / NCH)   // 1938
#define DT 61             // 61*128 >= 7752 dist tiles

// ---------------- packed fp32x2 helpers (bitwise = 2x scalar IEEE rn) ----------------
__device__ __forceinline__ unsigned long long pack2(float lo, float hi) {
    unsigned long long r;
    asm("mov.b64 %0, {%1, %2};" : "=l"(r) : "f"(lo), "f"(hi));
    return r;
}
__device__ __forceinline__ void fma2(unsigned long long& d, unsigned long long a,
                                     unsigned long long b) {
    asm("fma.rn.f32x2 %0, %1, %2, %0;" : "+l"(d) : "l"(a), "l"(b));
}
__device__ __forceinline__ float2 unpack2(unsigned long long v) {
    float2 r;
    asm("mov.b64 {%0, %1}, %2;" : "=f"(r.x), "=f"(r.y) : "l"(v));
    return r;
}

// ---------------- scratch (device globals; no allocation allowed) ----------------
__device__ float g_pts0[BB * NN * 3];
__device__ float g_sq[BB * NN];
__device__ float g_g81[BB * NN * 81];
__device__ float g_hA[BB * NN * 96];
__device__ float g_hB[BB * NN * 96];
__device__ int   g_idx[BB * NN * KK];
__device__ float g_bd[BB * NN * NCH * KK];
__device__ int   g_bi[BB * NN * NCH * KK];
__device__ float g_dist[(size_t)BB * NN * NN];   // D[b][m][q]
// interleaved transposed weights: [c][o] -> (we, wa)
__device__ float2 g_wEA1[162 * 96];
__device__ float2 g_wEA2[192 * 96];
__device__ float2 g_wEA3[192 * 32];

// XLA-GPU 16-element reduction tree
__device__ __forceinline__ float tree_sum16(const float* v) {
    float s8[8];
#pragma unroll
    for (int l = 0; l < 8; ++l) s8[l] = __fadd_rn(v[l], v[l + 8]);
    float s4[4];
#pragma unroll
    for (int l = 0; l < 4; ++l) s4[l] = __fadd_rn(s8[l], s8[l + 4]);
    float s2[2];
#pragma unroll
    for (int l = 0; l < 2; ++l) s2[l] = __fadd_rn(s4[l], s4[l + 2]);
    return __fadd_rn(s2[0], s2[1]);
}

// ---------------- fused weight transposes -> interleaved (we, wa) ----------------
__global__ void transpose_all_kernel(const float* __restrict__ e1, const float* __restrict__ a1,
                                     const float* __restrict__ e2, const float* __restrict__ a2,
                                     const float* __restrict__ e3, const float* __restrict__ a3,
                                     float2* __restrict__ w1, float2* __restrict__ w2,
                                     float2* __restrict__ w3) {
    int t = blockIdx.x * blockDim.x + threadIdx.x;
    if (t < 162 * 96) {
        int c = t / 96, o = t - c * 96;
        w1[t] = make_float2(e1[o * 162 + c], a1[o * 162 + c]);
        return;
    }
    t -= 162 * 96;
    if (t < 192 * 96) {
        int c = t / 96, o = t - c * 96;
        w2[t] = make_float2(e2[o * 192 + c], a2[o * 192 + c]);
        return;
    }
    t -= 192 * 96;
    if (t < 192 * 32) {
        int c = t / 32, o = t - c * 32;
        float2 v = make_float2(0.f, 0.f);
        if (o < 9) { v.x = e3[o * 192 + c]; v.y = a3[o * 192 + c]; }
        w3[t] = v;
    }
}

// ---------------- build: depth fuse, loc points, guidance graph gather ----------------
__global__ void build_kernel(const float* __restrict__ guidance,
                             const float* __restrict__ ini,
                             const float* __restrict__ sparse,
                             float* __restrict__ pts,
                             float* __restrict__ sq,
                             float* __restrict__ g81, int b) {
    int n = blockIdx.x * blockDim.x + threadIdx.x;
    if (n >= NN) return;
    int i = n / WG;
    int j = n - i * WG;

    int rd = 3 * i + 1;
    int cd = 3 * j;
    int doff = (b * HIN + rd) * WIN + cd;
    float sp = sparse[doff];
    float iv = ini[doff];
    float mask = (sp > 0.f) ? 1.f : ((sp < 0.f) ? -1.f : 0.f);
    float d = __fadd_rn(__fmul_rn(__fsub_rn(1.f, mask), iv), __fmul_rn(mask, sp));

    const float cxf = 156.52237935402365f;
    const float fxf = 291.31224083868975f;
    const float cyf = 119.22194813310193f;
    const float fyf = 291.3455163549432f;
    float x3 = __fdiv_rn(__fsub_rn((float)j, cxf), fxf);
    float y3 = __fdiv_rn(__fsub_rn((float)i, cyf), fyf);
    float l0 = __fmul_rn(__fmul_rn(x3, d), 3.0f);
    float l1 = __fmul_rn(__fmul_rn(y3, d), 3.0f);
    float l2 = d;

    int base = b * NN + n;
    pts[base * 3 + 0] = l0;
    pts[base * 3 + 1] = l1;
    pts[base * 3 + 2] = l2;
    float p0 = __fmul_rn(l0, l0);
    float p1 = __fmul_rn(l1, l1);
    float p2 = __fmul_rn(l2, l2);
    sq[base] = __fadd_rn(__fadd_rn(p0, p2), p1);

    const float* gb = guidance + (size_t)b * 81 * HIN * WIN;
    float* go = g81 + (size_t)base * 81;
#pragma unroll
    for (int c = 0; c < 81; ++c) {
        int r = 3 * i + (c / 9) - 3;
        int cc = 3 * j + (c % 9) - 4;
        float v = 0.f;
        if (r >= 0 && r < HIN && cc >= 0 && cc < WIN)
            v = gb[(c * HIN + r) * WIN + cc];
        go[c] = v;
    }
}

// ---------------- top-16 insertion (ascending dist; ties keep earlier index) ------
__device__ __forceinline__ void knn_insert(float dist, int index, float* bd, int* bi) {
    if (dist < bd[KK - 1]) {
        bd[KK - 1] = dist;
        bi[KK - 1] = index;
#pragma unroll
        for (int jj = KK - 1; jj > 0; --jj) {
            if (bd[jj] < bd[jj - 1]) {
                float td = bd[jj]; bd[jj] = bd[jj - 1]; bd[jj - 1] = td;
                int ti = bi[jj]; bi[jj] = bi[jj - 1]; bi[jj - 1] = ti;
            }
        }
    }
}

__device__ __forceinline__ float knn_dist(float qsq, float dot, float csq) {
    return __fadd_rn(__fsub_rn(qsq, __fmul_rn(2.0f, dot)), csq);
}

// ---------------- KNN D=3, candidate-chunked ----------------
#define KNN_TILE 64

__global__ void __launch_bounds__(128) knn3_kernel(const float* __restrict__ pts,
                                                   const float* __restrict__ sqn,
                                                   float* __restrict__ bdo,
                                                   int* __restrict__ bio, int b) {
    __shared__ float s_c[KNN_TILE * 3];
    __shared__ float s_sq[KNN_TILE];

    int ch = blockIdx.y;
    int n = blockIdx.x * blockDim.x + threadIdx.x;
    bool valid = (n < NN);

    float q0 = 0.f, q1 = 0.f, q2 = 0.f, qsq = 0.f;
    if (valid) {
        size_t bn = (size_t)(b * NN + n);
        q0 = pts[bn * 3 + 0];
        q1 = pts[bn * 3 + 1];
        q2 = pts[bn * 3 + 2];
        qsq = sqn[bn];
    }

    float bd[KK]; int bi[KK];
#pragma unroll
    for (int k = 0; k < KK; ++k) { bd[k] = 3.0e38f; bi[k] = 0; }

    int mBeg = ch * CHSZ, mEnd = mBeg + CHSZ;
    for (int m0 = mBeg; m0 < mEnd; m0 += KNN_TILE) {
        __syncthreads();
        for (int t = threadIdx.x; t < KNN_TILE * 3; t += blockDim.x) {
            int mm = m0 + t / 3;
            s_c[t] = (mm < mEnd) ? pts[((size_t)b * NN + m0) * 3 + t] : 0.f;
        }
        for (int t = threadIdx.x; t < KNN_TILE; t += blockDim.x) {
            int mm = m0 + t;
            s_sq[t] = (mm < mEnd) ? sqn[b * NN + mm] : 3.0e38f;
        }
        __syncthreads();
        if (valid) {
#pragma unroll 4
            for (int t = 0; t < KNN_TILE; ++t) {
                float a = fmaf(q0, s_c[t * 3 + 0], 0.f);
                a = fmaf(q1, s_c[t * 3 + 1], a);
                a = fmaf(q2, s_c[t * 3 + 2], a);
                knn_insert(knn_dist(qsq, a, s_sq[t]), m0 + t, bd, bi);
            }
        }
    }
    if (valid) {
        size_t base = ((size_t)(b * NN + n) * NCH + ch) * KK;
#pragma unroll
        for (int k = 0; k < KK; ++k) { bdo[base + k] = bd[k]; bio[base + k] = bi[k]; }
    }
}

// ---------------- KNN96 phase 1: symmetric distance matrix, f32x2 packed ----------
__global__ void __launch_bounds__(256) knn96_dist_kernel(const float* __restrict__ pts,
                                                         const float* __restrict__ sqn,
                                                         float* __restrict__ D, int b) {
    extern __shared__ char smem_raw[];
    float* sQt = (float*)smem_raw;               // [96][128] channel-major queries
    float4* sC4 = (float4*)(sQt + 96 * 128);     // [24][128] row-major candidates
    float* sqQ = (float*)(sC4 + 24 * 128);       // [128]
    float* sqC = sqQ + 128;                      // [128]

    int ti = blockIdx.y, tj = blockIdx.x;
    if (tj < ti) return;
    int I = ti * 128, J = tj * 128;
    int tid = threadIdx.x;
    int tx = tid & 15, ty = tid >> 4;

    const float4* P4 = (const float4*)(pts + (size_t)b * NN * 96);
    for (int idx = tid; idx < 128 * 24; idx += 256) {
        int row = idx & 127;
        int c4 = idx >> 7;
        int qr = I + row; int qc = (qr < NN) ? qr : (NN - 1);
        int mr = J + row; int mc = (mr < NN) ? mr : (NN - 1);
        float4 qv = P4[(size_t)qc * 24 + c4];
        sQt[(c4 * 4 + 0) * 128 + row] = qv.x;
        sQt[(c4 * 4 + 1) * 128 + row] = qv.y;
        sQt[(c4 * 4 + 2) * 128 + row] = qv.z;
        sQt[(c4 * 4 + 3) * 128 + row] = qv.w;
        sC4[c4 * 128 + row] = P4[(size_t)mc * 24 + c4];
    }
    if (tid < 128) {
        int qr = I + tid; sqQ[tid] = (qr < NN) ? sqn[b * NN + qr] : 0.f;
        int mr = J + tid; sqC[tid] = (mr < NN) ? sqn[b * NN + mr] : 0.f;
    }
    __syncthreads();

    unsigned long long acc2[4][8];
#pragma unroll
    for (int rp = 0; rp < 4; ++rp)
#pragma unroll
        for (int s = 0; s < 8; ++s) acc2[rp][s] = 0ull;

    for (int c4 = 0; c4 < 24; ++c4) {
        float4 cv[8];
#pragma unroll
        for (int s = 0; s < 8; ++s) cv[s] = sC4[c4 * 128 + tx + 16 * s];
#pragma unroll
        for (int ch = 0; ch < 4; ++ch) {
            const float* qrow = sQt + (c4 * 4 + ch) * 128 + 8 * ty;
            ulonglong2 qa = *(const ulonglong2*)(qrow);
            ulonglong2 qb = *(const ulonglong2*)(qrow + 4);
            unsigned long long qp0 = qa.x, qp1 = qa.y, qp2 = qb.x, qp3 = qb.y;
#pragma unroll
            for (int s = 0; s < 8; ++s) {
                float cvv = (ch == 0) ? cv[s].x : (ch == 1) ? cv[s].y
                          : (ch == 2) ? cv[s].z : cv[s].w;
                unsigned long long dup = pack2(cvv, cvv);
                fma2(acc2[0][s], qp0, dup);
                fma2(acc2[1][s], qp1, dup);
                fma2(acc2[2][s], qp2, dup);
                fma2(acc2[3][s], qp3, dup);
            }
        }
    }

    float sqq[8], sqc[8];
#pragma unroll
    for (int r = 0; r < 8; ++r) sqq[r] = sqQ[8 * ty + r];
#pragma unroll
    for (int s = 0; s < 8; ++s) sqc[s] = sqC[tx + 16 * s];

    float* Db = D + (size_t)b * NN * NN;

    // entry B: query = m (col), cand = qi (row) -> D[qi][m]
#pragma unroll
    for (int rp = 0; rp < 4; ++rp) {
#pragma unroll
        for (int h = 0; h < 2; ++h) {
            int r = 2 * rp + h;
            int qi = I + 8 * ty + r;
            if (qi < NN) {
                size_t ro = (size_t)qi * NN;
#pragma unroll
                for (int s = 0; s < 8; ++s) {
                    float2 dv = unpack2(acc2[rp][s]);
                    float dot = h ? dv.y : dv.x;
                    int m = J + tx + 16 * s;
                    if (m < NN) Db[ro + m] = knn_dist(sqc[s], dot, sqq[r]);
                }
            }
        }
    }

    // entry A: query = qi, cand = m -> D[m][qi], staged smem transpose
    __syncthreads();
    float* T = (float*)smem_raw;   // [128][132]
#pragma unroll
    for (int rp = 0; rp < 4; ++rp)
#pragma unroll
        for (int s = 0; s < 8; ++s) {
            float2 dv = unpack2(acc2[rp][s]);
            int col = tx + 16 * s;
            T[col * 132 + 8 * ty + 2 * rp + 0] = knn_dist(sqq[2 * rp + 0], dv.x, sqc[s]);
            T[col * 132 + 8 * ty + 2 * rp + 1] = knn_dist(sqq[2 * rp + 1], dv.y, sqc[s]);
        }
    __syncthreads();
    for (int idx = tid; idx < 128 * 128; idx += 256) {
        int mloc = idx >> 7, q = idx & 127;
        int m = J + mloc, qg = I + q;
        if (m < NN && qg < NN)
            Db[(size_t)m * NN + qg] = T[mloc * 132 + q];
    }
}

// ---------------- KNN96 phase 2: chunked top-16 selection over D rows ----------------
__global__ void __launch_bounds__(128) knn96_select_kernel(const float* __restrict__ D,
                                                           float* __restrict__ bdo,
                                                           int* __restrict__ bio, int b) {
    int ch = blockIdx.y;
    int n = blockIdx.x * blockDim.x + threadIdx.x;
    if (n >= NN) return;
    const float* Db = D + (size_t)b * NN * NN;

    float bd[KK]; int bi[KK];
#pragma unroll
    for (int k = 0; k < KK; ++k) { bd[k] = 3.0e38f; bi[k] = 0; }

    int mBeg = ch * CHSZ, mEnd = mBeg + CHSZ;
    int m = mBeg;
    for (; m + 8 <= mEnd; m += 8) {
        float d0 = __ldcs(&Db[(size_t)(m + 0) * NN + n]);
        float d1 = __ldcs(&Db[(size_t)(m + 1) * NN + n]);
        float d2 = __ldcs(&Db[(size_t)(m + 2) * NN + n]);
        float d3 = __ldcs(&Db[(size_t)(m + 3) * NN + n]);
        float d4 = __ldcs(&Db[(size_t)(m + 4) * NN + n]);
        float d5 = __ldcs(&Db[(size_t)(m + 5) * NN + n]);
        float d6 = __ldcs(&Db[(size_t)(m + 6) * NN + n]);
        float d7 = __ldcs(&Db[(size_t)(m + 7) * NN + n]);
        knn_insert(d0, m + 0, bd, bi);
        knn_insert(d1, m + 1, bd, bi);
        knn_insert(d2, m + 2, bd, bi);
        knn_insert(d3, m + 3, bd, bi);
        knn_insert(d4, m + 4, bd, bi);
        knn_insert(d5, m + 5, bd, bi);
        knn_insert(d6, m + 6, bd, bi);
        knn_insert(d7, m + 7, bd, bi);
    }
    for (; m < mEnd; ++m)
        knn_insert(__ldcs(&Db[(size_t)m * NN + n]), m, bd, bi);

    size_t base = ((size_t)(b * NN + n) * NCH + ch) * KK;
#pragma unroll
    for (int k = 0; k < KK; ++k) { bdo[base + k] = bd[k]; bio[base + k] = bi[k]; }
}

// ---------------- stable NCH-way merge of per-chunk top-16 lists ----------------
__global__ void knn_merge_kernel(const float* __restrict__ bdall,
                                 const int* __restrict__ biall,
                                 int* __restrict__ out, int b) {
    int q = blockIdx.x * blockDim.x + threadIdx.x;
    if (q >= NN) return;
    q += b * NN;
    int p[NCH];
#pragma unroll
    for (int ch = 0; ch < NCH; ++ch) p[ch] = 0;
    size_t base = (size_t)q * NCH * KK;
#pragma unroll
    for (int s = 0; s < KK; ++s) {
        float best = 3.4e38f;
        int bch = 0;
#pragma unroll
        for (int ch = 0; ch < NCH; ++ch) {
            float dv = bdall[base + ch * KK + p[ch]];
            if (dv < best) { best = dv; bch = ch; }
        }
        out[(size_t)q * KK + s] = biall[base + bch * KK + p[bch]];
        p[bch]++;
    }
}

// ---------------- per-edge attention: prefix-halving GEMM, k-pair packed f32x2 ------
template <int C, int O, int OP, bool SQ, bool FIN>
__global__ void edge_attn_kernel(const float* __restrict__ X,
                                 const int* __restrict__ idx,
                                 const float2* __restrict__ wEA,
                                 const float* __restrict__ be,
                                 const float* __restrict__ ba,
                                 float* __restrict__ out,
                                 float* __restrict__ sqout, int b) {
    constexpr int NW = OP / 32;
    constexpr int KS = 20;   // row stride: 80B, 16B-aligned for LDS.128
    __shared__ __align__(16) float sh_xi[2][C];
    __shared__ __align__(16) float sh_hd[2][C][KS];
    __shared__ float sh_out[2][96];

    int n0 = blockIdx.x * 2;
    int tid = threadIdx.x;

    for (int t = tid; t < 2 * C; t += blockDim.x) {
        int nodeL = t / C, c = t - nodeL * C;
        sh_xi[nodeL][c] = X[((size_t)(b * NN + n0 + nodeL)) * C + c];
    }
    for (int t = tid; t < 2 * KK * C; t += blockDim.x) {
        int nodeL = t / (KK * C);
        int r = t - nodeL * (KK * C);
        int k = r / C, c = r - k * C;
        size_t bn = (size_t)(b * NN + n0 + nodeL);
        float xi = X[bn * C + c];
        int j = idx[bn * KK + k];
        sh_hd[nodeL][c][k] = __fsub_rn(X[((size_t)(b * NN + j)) * C + c], xi);
    }
    __syncthreads();

    int warp = tid >> 5, lane = tid & 31;
    int nodeL = warp / NW;
    int og = (warp % NW) * 32 + lane;

    const unsigned long long* w64 = (const unsigned long long*)wEA;

    unsigned long long accP = 0ull;
    for (int c = 0; c < C; ++c) {
        unsigned long long w = __ldg(&w64[c * OP + og]);
        float xv = sh_xi[nodeL][c];
        fma2(accP, pack2(xv, xv), w);
    }
    float2 pref = unpack2(accP);

    unsigned long long accE2[KK / 2], accA2[KK / 2];
#pragma unroll
    for (int kp = 0; kp < KK / 2; ++kp) {
        accE2[kp] = pack2(pref.x, pref.x);
        accA2[kp] = pack2(pref.y, pref.y);
    }

    for (int c = 0; c < C; ++c) {
        float2 w = __ldg(&wEA[(C + c) * OP + og]);
        unsigned long long wd_e = pack2(w.x, w.x);
        unsigned long long wd_a = pack2(w.y, w.y);
        const ulonglong2* hrow = (const ulonglong2*)(&sh_hd[nodeL][c][0]);
#pragma unroll
        for (int kq = 0; kq < KK / 4; ++kq) {
            ulonglong2 h4 = hrow[kq];
            fma2(accE2[2 * kq + 0], h4.x, wd_e);
            fma2(accA2[2 * kq + 0], h4.x, wd_a);
            fma2(accE2[2 * kq + 1], h4.y, wd_e);
            fma2(accA2[2 * kq + 1], h4.y, wd_a);
        }
    }

    float eb = (og < O) ? __ldg(&be[og]) : 0.f;
    float ab = (og < O) ? __ldg(&ba[og]) : 0.f;
    float ev[KK], la[KK];
#pragma unroll
    for (int kp = 0; kp < KK / 2; ++kp) {
        float2 e2 = unpack2(accE2[kp]);
        float2 a2 = unpack2(accA2[kp]);
        ev[2 * kp + 0] = __fadd_rn(e2.x, eb);
        ev[2 * kp + 1] = __fadd_rn(e2.y, eb);
        la[2 * kp + 0] = __fadd_rn(a2.x, ab);
        la[2 * kp + 1] = __fadd_rn(a2.y, ab);
    }
    float m = la[0];
#pragma unroll
    for (int k = 1; k < KK; ++k) m = fmaxf(m, la[k]);
    float ex[KK];
#pragma unroll
    for (int k = 0; k < KK; ++k) ex[k] = expf(__fsub_rn(la[k], m));
    float S = tree_sum16(ex);
    float ea[KK];
#pragma unroll
    for (int k = 0; k < KK; ++k) {
        float av = __fdiv_rn(ex[k], S);
        ea[k] = __fmul_rn(ev[k], av);
    }
    float num = tree_sum16(ea);

    int n = n0 + nodeL;
    if (FIN) {
        if (og < O) {
            int i = n / WG, j = n - i * WG;
            int r = og / 3, s = og - r * 3;
            int col = 3 * j + s;
            if (col >= 1 && col <= WIN)
                out[((size_t)b * HIN + 3 * i + r) * WIN + (col - 1)] = num;
        }
    } else {
        if (og < O) out[((size_t)(b * NN + n)) * O + og] = num;
    }

    if (SQ) {
        if (og < O) sh_out[nodeL][og] = num;
        __syncthreads();
        if (warp < 2) {
            float x0 = sh_out[warp][lane];
            float x1 = sh_out[warp][lane + 32];
            float x2 = sh_out[warp][lane + 64];
            float p = __fadd_rn(__fadd_rn(__fmul_rn(x0, x0), __fmul_rn(x1, x1)),
                                __fmul_rn(x2, x2));
#pragma unroll
            for (int off = 16; off > 0; off >>= 1)
                p = __fadd_rn(p, __shfl_down_sync(0xffffffffu, p, off));
            if (lane == 0) sqout[b * NN + n0 + warp] = p;
        }
    }
}

// ---------------- launch ----------------
#define GETSYM(p, sym) do { void* _tmp; cudaGetSymbolAddress(&_tmp, sym); p = _tmp; } while (0)

#define DIST_SMEM (96 * 128 * 4 + 24 * 128 * 16 + 2 * 128 * 4)   // 99328 bytes

extern "C" void kernel_launch(void* const* d_in, const int* in_sizes, int n_in,
                              void* d_out, int out_size) {
    const float* guidance = (const float*)d_in[0];
    const float* ini      = (const float*)d_in[1];
    const float* sparse   = (const float*)d_in[2];
    const float* e_w1 = (const float*)d_in[3];
    const float* e_b1 = (const float*)d_in[4];
    const float* a_w1 = (const float*)d_in[5];
    const float* a_b1 = (const float*)d_in[6];
    const float* e_w2 = (const float*)d_in[7];
    const float* e_b2 = (const float*)d_in[8];
    const float* a_w2 = (const float*)d_in[9];
    const float* a_b2 = (const float*)d_in[10];
    const float* e_w3 = (const float*)d_in[11];
    const float* e_b3 = (const float*)d_in[12];
    const float* a_w3 = (const float*)d_in[13];
    const float* a_b3 = (const float*)d_in[14];
    float* out = (float*)d_out;

    void *p_pts0, *p_sq, *p_g81, *p_hA, *p_hB, *p_idx, *p_bd, *p_bi, *p_dist;
    void *p_w1, *p_w2, *p_w3;
    GETSYM(p_pts0, g_pts0); GETSYM(p_sq, g_sq); GETSYM(p_g81, g_g81);
    GETSYM(p_hA, g_hA); GETSYM(p_hB, g_hB); GETSYM(p_idx, g_idx);
    GETSYM(p_bd, g_bd); GETSYM(p_bi, g_bi); GETSYM(p_dist, g_dist);
    GETSYM(p_w1, g_wEA1); GETSYM(p_w2, g_wEA2); GETSYM(p_w3, g_wEA3);

    float* pts0 = (float*)p_pts0;  float* sqv = (float*)p_sq;  float* g81 = (float*)p_g81;
    float* hA = (float*)p_hA;      float* hB = (float*)p_hB;
    int* idxb = (int*)p_idx;
    float* bd = (float*)p_bd;      int* bi = (int*)p_bi;
    float* dist = (float*)p_dist;
    float2* wEA1 = (float2*)p_w1;  float2* wEA2 = (float2*)p_w2;  float2* wEA3 = (float2*)p_w3;

    static cudaStream_t s2 = nullptr;
    static cudaEvent_t evFork = nullptr, evJoin = nullptr;
    static int init_done = 0;
    if (!init_done) {
        cudaFuncSetAttribute(knn96_dist_kernel,
                             cudaFuncAttributeMaxDynamicSharedMemorySize, DIST_SMEM);
        cudaStreamCreateWithFlags(&s2, cudaStreamNonBlocking);
        cudaEventCreateWithFlags(&evFork, cudaEventDisableTiming);
        cudaEventCreateWithFlags(&evJoin, cudaEventDisableTiming);
        init_done = 1;
    }

    dim3 gN((NN + 127) / 128);
    dim3 gK((NN + 127) / 128, NCH);
    dim3 gE(NN / 2);
    dim3 gD(DT, DT);

    // shared preamble on the capture (legacy) stream
    transpose_all_kernel<<<(162 * 96 + 192 * 96 + 192 * 32 + 255) / 256, 256>>>(
        e_w1, a_w1, e_w2, a_w2, e_w3, a_w3, wEA1, wEA2, wEA3);

    // fork: batch 1 chain on s2, batch 0 chain on legacy stream
    cudaEventRecord(evFork, 0);
    cudaStreamWaitEvent(s2, evFork, 0);

    for (int b = 0; b < BB; ++b) {
        cudaStream_t st = (b == 0) ? (cudaStream_t)0 : s2;

        build_kernel<<<gN, 128, 0, st>>>(guidance, ini, sparse, pts0, sqv, g81, b);

        // layer 1
        knn3_kernel<<<gK, 128, 0, st>>>(pts0, sqv, bd, bi, b);
        knn_merge_kernel<<<gN, 128, 0, st>>>(bd, bi, idxb, b);
        edge_attn_kernel<81, 96, 96, true, false><<<gE, 192, 0, st>>>(
            g81, idxb, wEA1, e_b1, a_b1, hA, sqv, b);

        // layer 2
        knn96_dist_kernel<<<gD, 256, DIST_SMEM, st>>>(hA, sqv, dist, b);
        knn96_select_kernel<<<gK, 128, 0, st>>>(dist, bd, bi, b);
        knn_merge_kernel<<<gN, 128, 0, st>>>(bd, bi, idxb, b);
        edge_attn_kernel<96, 96, 96, true, false><<<gE, 192, 0, st>>>(
            hA, idxb, wEA2, e_b2, a_b2, hB, sqv, b);

        // layer 3: attention scatters straight into d_out
        knn96_dist_kernel<<<gD, 256, DIST_SMEM, st>>>(hB, sqv, dist, b);
        knn96_select_kernel<<<gK, 128, 0, st>>>(dist, bd, bi, b);
        knn_merge_kernel<<<gN, 128, 0, st>>>(bd, bi, idxb, b);
        edge_attn_kernel<96, 9, 32, false, true><<<gE, 64, 0, st>>>(
            hB, idxb, wEA3, e_b3, a_b3, out, nullptr, b);
    }

    // join
    cudaEventRecord(evJoin, s2);
    cudaStreamWaitEvent((cudaStream_t)0, evJoin, 0);
}

// round 16
// speedup vs baseline: 1.0810x; 1.0810x over previous
#include <cuda_runtime.h>
#include <math.h>

#define HIN 228
#define WIN 304
#define HG 76
#define WG 102
#define NN 7752
#define BB 2
#define KK 16
#define NCH 8
#define CHSZ (NN / NCH)   // 969
#define DT 61             // 61*128 >= 7752 dist tiles

// ---------------- packed fp32x2 helpers (bitwise = 2x scalar IEEE rn) ----------------
__device__ __forceinline__ unsigned long long pack2(float lo, float hi) {
    unsigned long long r;
    asm("mov.b64 %0, {%1, %2};" : "=l"(r) : "f"(lo), "f"(hi));
    return r;
}
__device__ __forceinline__ void fma2(unsigned long long& d, unsigned long long a,
                                     unsigned long long b) {
    asm("fma.rn.f32x2 %0, %1, %2, %0;" : "+l"(d) : "l"(a), "l"(b));
}
__device__ __forceinline__ float2 unpack2(unsigned long long v) {
    float2 r;
    asm("mov.b64 {%0, %1}, %2;" : "=f"(r.x), "=f"(r.y) : "l"(v));
    return r;
}

// ---------------- scratch (device globals; no allocation allowed) ----------------
__device__ float g_pts0[BB * NN * 3];
__device__ float g_sq[BB * NN];
__device__ float g_g81[BB * NN * 81];
__device__ float g_hA[BB * NN * 96];
__device__ float g_hB[BB * NN * 96];
__device__ int   g_idx[BB * NN * KK];
__device__ float g_bd[BB * NN * NCH * KK];
__device__ int   g_bi[BB * NN * NCH * KK];
__device__ float g_dist[(size_t)BB * NN * NN];   // D[b][m][q] = dist(query q, cand m)
// interleaved transposed weights: [c][o] -> (we, wa)
__device__ float2 g_wEA1[162 * 96];
__device__ float2 g_wEA2[192 * 96];
__device__ float2 g_wEA3[192 * 32];

// XLA-GPU 16-element reduction tree
__device__ __forceinline__ float tree_sum16(const float* v) {
    float s8[8];
#pragma unroll
    for (int l = 0; l < 8; ++l) s8[l] = __fadd_rn(v[l], v[l + 8]);
    float s4[4];
#pragma unroll
    for (int l = 0; l < 4; ++l) s4[l] = __fadd_rn(s8[l], s8[l + 4]);
    float s2[2];
#pragma unroll
    for (int l = 0; l < 2; ++l) s2[l] = __fadd_rn(s4[l], s4[l + 2]);
    return __fadd_rn(s2[0], s2[1]);
}

// ---------------- fused weight transposes -> interleaved (we, wa) ----------------
__global__ void transpose_all_kernel(const float* __restrict__ e1, const float* __restrict__ a1,
                                     const float* __restrict__ e2, const float* __restrict__ a2,
                                     const float* __restrict__ e3, const float* __restrict__ a3,
                                     float2* __restrict__ w1, float2* __restrict__ w2,
                                     float2* __restrict__ w3) {
    int t = blockIdx.x * blockDim.x + threadIdx.x;
    if (t < 162 * 96) {
        int c = t / 96, o = t - c * 96;
        w1[t] = make_float2(e1[o * 162 + c], a1[o * 162 + c]);
        return;
    }
    t -= 162 * 96;
    if (t < 192 * 96) {
        int c = t / 96, o = t - c * 96;
        w2[t] = make_float2(e2[o * 192 + c], a2[o * 192 + c]);
        return;
    }
    t -= 192 * 96;
    if (t < 192 * 32) {
        int c = t / 32, o = t - c * 32;
        float2 v = make_float2(0.f, 0.f);
        if (o < 9) { v.x = e3[o * 192 + c]; v.y = a3[o * 192 + c]; }
        w3[t] = v;
    }
}

// ---------------- build: depth fuse, loc points, guidance graph gather ----------------
__global__ void build_kernel(const float* __restrict__ guidance,
                             const float* __restrict__ ini,
                             const float* __restrict__ sparse,
                             float* __restrict__ pts,
                             float* __restrict__ sq,
                             float* __restrict__ g81) {
    int n = blockIdx.x * blockDim.x + threadIdx.x;
    int b = blockIdx.y;
    if (n >= NN) return;
    int i = n / WG;
    int j = n - i * WG;

    int rd = 3 * i + 1;
    int cd = 3 * j;
    int doff = (b * HIN + rd) * WIN + cd;
    float sp = sparse[doff];
    float iv = ini[doff];
    float mask = (sp > 0.f) ? 1.f : ((sp < 0.f) ? -1.f : 0.f);
    float d = __fadd_rn(__fmul_rn(__fsub_rn(1.f, mask), iv), __fmul_rn(mask, sp));

    const float cxf = 156.52237935402365f;
    const float fxf = 291.31224083868975f;
    const float cyf = 119.22194813310193f;
    const float fyf = 291.3455163549432f;
    float x3 = __fdiv_rn(__fsub_rn((float)j, cxf), fxf);
    float y3 = __fdiv_rn(__fsub_rn((float)i, cyf), fyf);
    float l0 = __fmul_rn(__fmul_rn(x3, d), 3.0f);
    float l1 = __fmul_rn(__fmul_rn(y3, d), 3.0f);
    float l2 = d;

    int base = b * NN + n;
    pts[base * 3 + 0] = l0;
    pts[base * 3 + 1] = l1;
    pts[base * 3 + 2] = l2;
    float p0 = __fmul_rn(l0, l0);
    float p1 = __fmul_rn(l1, l1);
    float p2 = __fmul_rn(l2, l2);
    sq[base] = __fadd_rn(__fadd_rn(p0, p2), p1);

    const float* gb = guidance + (size_t)b * 81 * HIN * WIN;
    float* go = g81 + (size_t)base * 81;
#pragma unroll
    for (int c = 0; c < 81; ++c) {
        int r = 3 * i + (c / 9) - 3;
        int cc = 3 * j + (c % 9) - 4;
        float v = 0.f;
        if (r >= 0 && r < HIN && cc >= 0 && cc < WIN)
            v = gb[(c * HIN + r) * WIN + cc];
        go[c] = v;
    }
}

// ---------------- top-16 insertion (ascending dist; ties keep earlier index) ------
__device__ __forceinline__ void knn_insert(float dist, int index, float* bd, int* bi) {
    if (dist < bd[KK - 1]) {
        bd[KK - 1] = dist;
        bi[KK - 1] = index;
#pragma unroll
        for (int jj = KK - 1; jj > 0; --jj) {
            if (bd[jj] < bd[jj - 1]) {
                float td = bd[jj]; bd[jj] = bd[jj - 1]; bd[jj - 1] = td;
                int ti = bi[jj]; bi[jj] = bi[jj - 1]; bi[jj - 1] = ti;
            }
        }
    }
}

__device__ __forceinline__ float knn_dist(float qsq, float dot, float csq) {
    return __fadd_rn(__fsub_rn(qsq, __fmul_rn(2.0f, dot)), csq);
}

// ---------------- KNN D=3, candidate-chunked ----------------
#define KNN_TILE 64

__global__ void __launch_bounds__(128) knn3_kernel(const float* __restrict__ pts,
                                                   const float* __restrict__ sqn,
                                                   float* __restrict__ bdo,
                                                   int* __restrict__ bio) {
    __shared__ float s_c[KNN_TILE * 3];
    __shared__ float s_sq[KNN_TILE];

    int b = blockIdx.z;
    int ch = blockIdx.y;
    int n = blockIdx.x * blockDim.x + threadIdx.x;
    bool valid = (n < NN);

    float q0 = 0.f, q1 = 0.f, q2 = 0.f, qsq = 0.f;
    if (valid) {
        size_t bn = (size_t)(b * NN + n);
        q0 = pts[bn * 3 + 0];
        q1 = pts[bn * 3 + 1];
        q2 = pts[bn * 3 + 2];
        qsq = sqn[bn];
    }

    float bd[KK]; int bi[KK];
#pragma unroll
    for (int k = 0; k < KK; ++k) { bd[k] = 3.0e38f; bi[k] = 0; }

    int mBeg = ch * CHSZ, mEnd = mBeg + CHSZ;
    for (int m0 = mBeg; m0 < mEnd; m0 += KNN_TILE) {
        __syncthreads();
        for (int t = threadIdx.x; t < KNN_TILE * 3; t += blockDim.x) {
            int mm = m0 + t / 3;
            s_c[t] = (mm < mEnd) ? pts[((size_t)b * NN + m0) * 3 + t] : 0.f;
        }
        for (int t = threadIdx.x; t < KNN_TILE; t += blockDim.x) {
            int mm = m0 + t;
            s_sq[t] = (mm < mEnd) ? sqn[b * NN + mm] : 3.0e38f;
        }
        __syncthreads();
        if (valid) {
#pragma unroll 4
            for (int t = 0; t < KNN_TILE; ++t) {
                float a = fmaf(q0, s_c[t * 3 + 0], 0.f);
                a = fmaf(q1, s_c[t * 3 + 1], a);
                a = fmaf(q2, s_c[t * 3 + 2], a);
                knn_insert(knn_dist(qsq, a, s_sq[t]), m0 + t, bd, bi);
            }
        }
    }
    if (valid) {
        size_t base = ((size_t)(b * NN + n) * NCH + ch) * KK;
#pragma unroll
        for (int k = 0; k < KK; ++k) { bdo[base + k] = bd[k]; bio[base + k] = bi[k]; }
    }
}

// ---------------- KNN96 phase 1: symmetric distance matrix, f32x2 packed ----------
__global__ void __launch_bounds__(256) knn96_dist_kernel(const float* __restrict__ pts,
                                                         const float* __restrict__ sqn,
                                                         float* __restrict__ D) {
    extern __shared__ char smem_raw[];
    float* sQt = (float*)smem_raw;               // [96][128] channel-major queries
    float4* sC4 = (float4*)(sQt + 96 * 128);     // [24][128] row-major candidates
    float* sqQ = (float*)(sC4 + 24 * 128);       // [128]
    float* sqC = sqQ + 128;                      // [128]

    int b = blockIdx.z;
    int ti = blockIdx.y, tj = blockIdx.x;
    if (tj < ti) return;
    int I = ti * 128, J = tj * 128;
    int tid = threadIdx.x;
    int tx = tid & 15, ty = tid >> 4;

    const float4* P4 = (const float4*)(pts + (size_t)b * NN * 96);
    for (int idx = tid; idx < 128 * 24; idx += 256) {
        int row = idx & 127;
        int c4 = idx >> 7;
        int qr = I + row; int qc = (qr < NN) ? qr : (NN - 1);
        int mr = J + row; int mc = (mr < NN) ? mr : (NN - 1);
        float4 qv = P4[(size_t)qc * 24 + c4];
        sQt[(c4 * 4 + 0) * 128 + row] = qv.x;
        sQt[(c4 * 4 + 1) * 128 + row] = qv.y;
        sQt[(c4 * 4 + 2) * 128 + row] = qv.z;
        sQt[(c4 * 4 + 3) * 128 + row] = qv.w;
        sC4[c4 * 128 + row] = P4[(size_t)mc * 24 + c4];
    }
    if (tid < 128) {
        int qr = I + tid; sqQ[tid] = (qr < NN) ? sqn[b * NN + qr] : 0.f;
        int mr = J + tid; sqC[tid] = (mr < NN) ? sqn[b * NN + mr] : 0.f;
    }
    __syncthreads();

    unsigned long long acc2[4][8];
#pragma unroll
    for (int rp = 0; rp < 4; ++rp)
#pragma unroll
        for (int s = 0; s < 8; ++s) acc2[rp][s] = 0ull;

    for (int c4 = 0; c4 < 24; ++c4) {
        float4 cv[8];
#pragma unroll
        for (int s = 0; s < 8; ++s) cv[s] = sC4[c4 * 128 + tx + 16 * s];
#pragma unroll
        for (int ch = 0; ch < 4; ++ch) {
            const float* qrow = sQt + (c4 * 4 + ch) * 128 + 8 * ty;
            ulonglong2 qa = *(const ulonglong2*)(qrow);
            ulonglong2 qb = *(const ulonglong2*)(qrow + 4);
            unsigned long long qp0 = qa.x, qp1 = qa.y, qp2 = qb.x, qp3 = qb.y;
#pragma unroll
            for (int s = 0; s < 8; ++s) {
                float cvv = (ch == 0) ? cv[s].x : (ch == 1) ? cv[s].y
                          : (ch == 2) ? cv[s].z : cv[s].w;
                unsigned long long dup = pack2(cvv, cvv);
                fma2(acc2[0][s], qp0, dup);
                fma2(acc2[1][s], qp1, dup);
                fma2(acc2[2][s], qp2, dup);
                fma2(acc2[3][s], qp3, dup);
            }
        }
    }

    float sqq[8], sqc[8];
#pragma unroll
    for (int r = 0; r < 8; ++r) sqq[r] = sqQ[8 * ty + r];
#pragma unroll
    for (int s = 0; s < 8; ++s) sqc[s] = sqC[tx + 16 * s];

    float* Db = D + (size_t)b * NN * NN;

    // entry B: query = m (col), cand = qi (row) -> D[qi][m]
#pragma unroll
    for (int rp = 0; rp < 4; ++rp) {
#pragma unroll
        for (int h = 0; h < 2; ++h) {
            int r = 2 * rp + h;
            int qi = I + 8 * ty + r;
            if (qi < NN) {
                size_t ro = (size_t)qi * NN;
#pragma unroll
                for (int s = 0; s < 8; ++s) {
                    float2 dv = unpack2(acc2[rp][s]);
                    float dot = h ? dv.y : dv.x;
                    int m = J + tx + 16 * s;
                    if (m < NN) Db[ro + m] = knn_dist(sqc[s], dot, sqq[r]);
                }
            }
        }
    }

    // entry A: query = qi, cand = m -> D[m][qi], staged smem transpose
    __syncthreads();
    float* T = (float*)smem_raw;   // [128][132]
#pragma unroll
    for (int rp = 0; rp < 4; ++rp)
#pragma unroll
        for (int s = 0; s < 8; ++s) {
            float2 dv = unpack2(acc2[rp][s]);
            int col = tx + 16 * s;
            T[col * 132 + 8 * ty + 2 * rp + 0] = knn_dist(sqq[2 * rp + 0], dv.x, sqc[s]);
            T[col * 132 + 8 * ty + 2 * rp + 1] = knn_dist(sqq[2 * rp + 1], dv.y, sqc[s]);
        }
    __syncthreads();
    for (int idx = tid; idx < 128 * 128; idx += 256) {
        int mloc = idx >> 7, q = idx & 127;
        int m = J + mloc, qg = I + q;
        if (m < NN && qg < NN)
            Db[(size_t)m * NN + qg] = T[mloc * 132 + q];
    }
}

// ---------------- KNN96 phase 2: chunked top-16 selection over D rows ----------------
__global__ void __launch_bounds__(128) knn96_select_kernel(const float* __restrict__ D,
                                                           float* __restrict__ bdo,
                                                           int* __restrict__ bio) {
    int b = blockIdx.z, ch = blockIdx.y;
    int n = blockIdx.x * blockDim.x + threadIdx.x;
    if (n >= NN) return;
    const float* Db = D + (size_t)b * NN * NN;

    float bd[KK]; int bi[KK];
#pragma unroll
    for (int k = 0; k < KK; ++k) { bd[k] = 3.0e38f; bi[k] = 0; }

    int mBeg = ch * CHSZ, mEnd = mBeg + CHSZ;
    int m = mBeg;
    for (; m + 4 <= mEnd; m += 4) {
        float d0 = __ldcs(&Db[(size_t)(m + 0) * NN + n]);
        float d1 = __ldcs(&Db[(size_t)(m + 1) * NN + n]);
        float d2 = __ldcs(&Db[(size_t)(m + 2) * NN + n]);
        float d3 = __ldcs(&Db[(size_t)(m + 3) * NN + n]);
        knn_insert(d0, m + 0, bd, bi);
        knn_insert(d1, m + 1, bd, bi);
        knn_insert(d2, m + 2, bd, bi);
        knn_insert(d3, m + 3, bd, bi);
    }
    for (; m < mEnd; ++m)
        knn_insert(__ldcs(&Db[(size_t)m * NN + n]), m, bd, bi);

    size_t base = ((size_t)(b * NN + n) * NCH + ch) * KK;
#pragma unroll
    for (int k = 0; k < KK; ++k) { bdo[base + k] = bd[k]; bio[base + k] = bi[k]; }
}

// ---------------- stable 8-way merge of per-chunk top-16 lists ----------------
__global__ void knn_merge_kernel(const float* __restrict__ bdall,
                                 const int* __restrict__ biall,
                                 int* __restrict__ out) {
    int q = blockIdx.x * blockDim.x + threadIdx.x;
    if (q >= BB * NN) return;
    int p[NCH];
#pragma unroll
    for (int ch = 0; ch < NCH; ++ch) p[ch] = 0;
    size_t base = (size_t)q * NCH * KK;
#pragma unroll
    for (int s = 0; s < KK; ++s) {
        float best = 3.4e38f;
        int bch = 0;
#pragma unroll
        for (int ch = 0; ch < NCH; ++ch) {
            float dv = bdall[base + ch * KK + p[ch]];
            if (dv < best) { best = dv; bch = ch; }
        }
        out[(size_t)q * KK + s] = biall[base + bch * KK + p[bch]];
        p[bch]++;
    }
}

// ---------------- per-edge attention: prefix-halving GEMM, k-pair packed f32x2 ------
// __launch_bounds__(192, 6): cap regs at 56 to raise occupancy (R12 profile: 64
// regs -> 45% occ, issue 62.6%). Register allocation does not affect arithmetic
// order -> bitwise identical.
template <int C, int O, int OP, bool SQ, bool FIN>
__global__ void __launch_bounds__(192, 6)
edge_attn_kernel(const float* __restrict__ X,
                 const int* __restrict__ idx,
                 const float2* __restrict__ wEA,
                 const float* __restrict__ be,
                 const float* __restrict__ ba,
                 float* __restrict__ out,
                 float* __restrict__ sqout) {
    constexpr int NW = OP / 32;
    constexpr int KS = 20;   // row stride: 80B, 16B-aligned for LDS.128
    __shared__ __align__(16) float sh_xi[2][C];
    __shared__ __align__(16) float sh_hd[2][C][KS];
    __shared__ float sh_out[2][96];

    int b = blockIdx.y;
    int n0 = blockIdx.x * 2;
    int tid = threadIdx.x;

    for (int t = tid; t < 2 * C; t += blockDim.x) {
        int nodeL = t / C, c = t - nodeL * C;
        sh_xi[nodeL][c] = X[((size_t)(b * NN + n0 + nodeL)) * C + c];
    }
    for (int t = tid; t < 2 * KK * C; t += blockDim.x) {
        int nodeL = t / (KK * C);
        int r = t - nodeL * (KK * C);
        int k = r / C, c = r - k * C;
        size_t bn = (size_t)(b * NN + n0 + nodeL);
        float xi = X[bn * C + c];
        int j = idx[bn * KK + k];
        sh_hd[nodeL][c][k] = __fsub_rn(X[((size_t)(b * NN + j)) * C + c], xi);
    }
    __syncthreads();

    int warp = tid >> 5, lane = tid & 31;
    int nodeL = warp / NW;
    int og = (warp % NW) * 32 + lane;

    const unsigned long long* w64 = (const unsigned long long*)wEA;

    unsigned long long accP = 0ull;
    for (int c = 0; c < C; ++c) {
        unsigned long long w = __ldg(&w64[c * OP + og]);
        float xv = sh_xi[nodeL][c];
        fma2(accP, pack2(xv, xv), w);
    }
    float2 pref = unpack2(accP);

    unsigned long long accE2[KK / 2], accA2[KK / 2];
#pragma unroll
    for (int kp = 0; kp < KK / 2; ++kp) {
        accE2[kp] = pack2(pref.x, pref.x);
        accA2[kp] = pack2(pref.y, pref.y);
    }

    for (int c = 0; c < C; ++c) {
        float2 w = __ldg(&wEA[(C + c) * OP + og]);
        unsigned long long wd_e = pack2(w.x, w.x);
        unsigned long long wd_a = pack2(w.y, w.y);
        const ulonglong2* hrow = (const ulonglong2*)(&sh_hd[nodeL][c][0]);
#pragma unroll
        for (int kq = 0; kq < KK / 4; ++kq) {
            ulonglong2 h4 = hrow[kq];
            fma2(accE2[2 * kq + 0], h4.x, wd_e);
            fma2(accA2[2 * kq + 0], h4.x, wd_a);
            fma2(accE2[2 * kq + 1], h4.y, wd_e);
            fma2(accA2[2 * kq + 1], h4.y, wd_a);
        }
    }

    float eb = (og < O) ? __ldg(&be[og]) : 0.f;
    float ab = (og < O) ? __ldg(&ba[og]) : 0.f;
    float ev[KK], la[KK];
#pragma unroll
    for (int kp = 0; kp < KK / 2; ++kp) {
        float2 e2 = unpack2(accE2[kp]);
        float2 a2 = unpack2(accA2[kp]);
        ev[2 * kp + 0] = __fadd_rn(e2.x, eb);
        ev[2 * kp + 1] = __fadd_rn(e2.y, eb);
        la[2 * kp + 0] = __fadd_rn(a2.x, ab);
        la[2 * kp + 1] = __fadd_rn(a2.y, ab);
    }
    float m = la[0];
#pragma unroll
    for (int k = 1; k < KK; ++k) m = fmaxf(m, la[k]);
    float ex[KK];
#pragma unroll
    for (int k = 0; k < KK; ++k) ex[k] = expf(__fsub_rn(la[k], m));
    float S = tree_sum16(ex);
    float ea[KK];
#pragma unroll
    for (int k = 0; k < KK; ++k) {
        float av = __fdiv_rn(ex[k], S);
        ea[k] = __fmul_rn(ev[k], av);
    }
    float num = tree_sum16(ea);

    int n = n0 + nodeL;
    if (FIN) {
        if (og < O) {
            int i = n / WG, j = n - i * WG;
            int r = og / 3, s = og - r * 3;
            int col = 3 * j + s;
            if (col >= 1 && col <= WIN)
                out[((size_t)b * HIN + 3 * i + r) * WIN + (col - 1)] = num;
        }
    } else {
        if (og < O) out[((size_t)(b * NN + n)) * O + og] = num;
    }

    if (SQ) {
        if (og < O) sh_out[nodeL][og] = num;
        __syncthreads();
        if (warp < 2) {
            float x0 = sh_out[warp][lane];
            float x1 = sh_out[warp][lane + 32];
            float x2 = sh_out[warp][lane + 64];
            float p = __fadd_rn(__fadd_rn(__fmul_rn(x0, x0), __fmul_rn(x1, x1)),
                                __fmul_rn(x2, x2));
#pragma unroll
            for (int off = 16; off > 0; off >>= 1)
                p = __fadd_rn(p, __shfl_down_sync(0xffffffffu, p, off));
            if (lane == 0) sqout[b * NN + n0 + warp] = p;
        }
    }
}

// ---------------- launch ----------------
#define GETSYM(p, sym) do { void* _tmp; cudaGetSymbolAddress(&_tmp, sym); p = _tmp; } while (0)

#define DIST_SMEM (96 * 128 * 4 + 24 * 128 * 16 + 2 * 128 * 4)   // 99328 bytes

extern "C" void kernel_launch(void* const* d_in, const int* in_sizes, int n_in,
                              void* d_out, int out_size) {
    const float* guidance = (const float*)d_in[0];
    const float* ini      = (const float*)d_in[1];
    const float* sparse   = (const float*)d_in[2];
    const float* e_w1 = (const float*)d_in[3];
    const float* e_b1 = (const float*)d_in[4];
    const float* a_w1 = (const float*)d_in[5];
    const float* a_b1 = (const float*)d_in[6];
    const float* e_w2 = (const float*)d_in[7];
    const float* e_b2 = (const float*)d_in[8];
    const float* a_w2 = (const float*)d_in[9];
    const float* a_b2 = (const float*)d_in[10];
    const float* e_w3 = (const float*)d_in[11];
    const float* e_b3 = (const float*)d_in[12];
    const float* a_w3 = (const float*)d_in[13];
    const float* a_b3 = (const float*)d_in[14];
    float* out = (float*)d_out;

    void *p_pts0, *p_sq, *p_g81, *p_hA, *p_hB, *p_idx, *p_bd, *p_bi, *p_dist;
    void *p_w1, *p_w2, *p_w3;
    GETSYM(p_pts0, g_pts0); GETSYM(p_sq, g_sq); GETSYM(p_g81, g_g81);
    GETSYM(p_hA, g_hA); GETSYM(p_hB, g_hB); GETSYM(p_idx, g_idx);
    GETSYM(p_bd, g_bd); GETSYM(p_bi, g_bi); GETSYM(p_dist, g_dist);
    GETSYM(p_w1, g_wEA1); GETSYM(p_w2, g_wEA2); GETSYM(p_w3, g_wEA3);

    float* pts0 = (float*)p_pts0;  float* sqv = (float*)p_sq;  float* g81 = (float*)p_g81;
    float* hA = (float*)p_hA;      float* hB = (float*)p_hB;
    int* idxb = (int*)p_idx;
    float* bd = (float*)p_bd;      int* bi = (int*)p_bi;
    float* dist = (float*)p_dist;
    float2* wEA1 = (float2*)p_w1;  float2* wEA2 = (float2*)p_w2;  float2* wEA3 = (float2*)p_w3;

    static int smem_set = 0;
    if (!smem_set) {
        cudaFuncSetAttribute(knn96_dist_kernel,
                             cudaFuncAttributeMaxDynamicSharedMemorySize, DIST_SMEM);
        smem_set = 1;
    }

    dim3 gN((NN + 127) / 128, BB);
    dim3 gK3((NN + 127) / 128, NCH, BB);
    dim3 gM((BB * NN + 127) / 128);
    dim3 gE(NN / 2, BB);
    dim3 gD(DT, DT, BB);
    dim3 gSel((NN + 127) / 128, NCH, BB);

    transpose_all_kernel<<<(162 * 96 + 192 * 96 + 192 * 32 + 255) / 256, 256>>>(
        e_w1, a_w1, e_w2, a_w2, e_w3, a_w3, wEA1, wEA2, wEA3);
    build_kernel<<<gN, 128>>>(guidance, ini, sparse, pts0, sqv, g81);

    // layer 1
    knn3_kernel<<<gK3, 128>>>(pts0, sqv, bd, bi);
    knn_merge_kernel<<<gM, 128>>>(bd, bi, idxb);
    edge_attn_kernel<81, 96, 96, true, false><<<gE, 192>>>(g81, idxb, wEA1, e_b1, a_b1, hA, sqv);

    // layer 2
    knn96_dist_kernel<<<gD, 256, DIST_SMEM>>>(hA, sqv, dist);
    knn96_select_kernel<<<gSel, 128>>>(dist, bd, bi);
    knn_merge_kernel<<<gM, 128>>>(bd, bi, idxb);
    edge_attn_kernel<96, 96, 96, true, false><<<gE, 192>>>(hA, idxb, wEA2, e_b2, a_b2, hB, sqv);

    // layer 3: attention scatters straight into d_out (pixel shuffle + slice)
    knn96_dist_kernel<<<gD, 256, DIST_SMEM>>>(hB, sqv, dist);
    knn96_select_kernel<<<gSel, 128>>>(dist, bd, bi);
    knn_merge_kernel<<<gM, 128>>>(bd, bi, idxb);
    edge_attn_kernel<96, 9, 32, false, true><<<gE, 64>>>(hB, idxb, wEA3, e_b3, a_b3, out, nullptr);
}